// round 9
// baseline (speedup 1.0000x reference)
#include <cuda_runtime.h>

#define EPT 4   // elements per thread

__device__ int g_adj_is_i64;   // 1 if adjacency buffer is int64-LE, else int32

__global__ void zero_detect_kernel(float* __restrict__ out, int n,
                                   const unsigned int* __restrict__ adj_words) {
    int i = blockIdx.x * blockDim.x + threadIdx.x;
    if (i < n) out[i] = 0.0f;
    if (blockIdx.x == 0 && threadIdx.x == 0) {
        // int64-LE indices < 2^31 => odd words of first 32 entries all zero.
        // Probe stays within first 256 bytes (in-bounds for both layouts).
        int all_zero = 1;
        for (int k = 1; k < 64; k += 2)
            if (adj_words[k] != 0u) { all_zero = 0; break; }
        g_adj_is_i64 = all_zero;
    }
}

__device__ __forceinline__ float fast_sigmoid(float x) {
    // sigmoid(x) = 0.5 * tanh(0.5x) + 0.5 ; tanh.approx.f32 = 1 MUFU op
    float t;
    asm("tanh.approx.f32 %0, %1;" : "=f"(t) : "f"(x * 0.5f));
    return fmaf(t, 0.5f, 0.5f);
}

__global__ __launch_bounds__(256, 2) void mesh_mlp_kernel(
    const float* __restrict__ points,        // [N_POINTS, 2]
    const void*  __restrict__ adj_raw,       // [N_ELEMS, 3] int32 (or int64)
    const float* __restrict__ W1, const float* __restrict__ b1,
    const float* __restrict__ W2, const float* __restrict__ b2,
    const float* __restrict__ W3, const float* __restrict__ b3,
    const float* __restrict__ W4, const float* __restrict__ b4,
    float* __restrict__ out,                 // [N_POINTS]
    int n_elems, int n_points)
{
    __shared__ float sW1[48], sb1[8];
    __shared__ float sW2[64], sb2[8];
    __shared__ float sW3[64], sb3[8];
    __shared__ float sW4[24], sb4[3];

    int t = threadIdx.x;
    if (t < 48) sW1[t] = W1[t];
    if (t < 8)  sb1[t] = b1[t];
    if (t < 64) sW2[t] = W2[t];
    if (t >= 64 && t < 72) sb2[t - 64] = b2[t - 64];
    if (t >= 128 && t < 192) sW3[t - 128] = W3[t - 128];
    if (t >= 192 && t < 200) sb3[t - 192] = b3[t - 192];
    if (t >= 200 && t < 224) sW4[t - 200] = W4[t - 200];
    if (t >= 224 && t < 227) sb4[t - 224] = b4[t - 224];
    __syncthreads();

    int e0 = (blockIdx.x * blockDim.x + t) * EPT;
    if (e0 >= n_elems) return;

    bool full = (e0 + EPT <= n_elems);
    int cnt = full ? EPT * 3 : (n_elems - e0) * 3;   // valid index count

    int idx[EPT * 3];
    if (!g_adj_is_i64) {                              // uniform branch
        const int* a = (const int*)adj_raw;
        if (full) {
            // 48 bytes, 16B-aligned (e0 multiple of 4 -> byte off 48*thread)
            const int4* a4 = (const int4*)(a + (size_t)e0 * 3);
            int4 v0 = a4[0], v1 = a4[1], v2 = a4[2];
            idx[0] = v0.x; idx[1]  = v0.y; idx[2]  = v0.z; idx[3]  = v0.w;
            idx[4] = v1.x; idx[5]  = v1.y; idx[6]  = v1.z; idx[7]  = v1.w;
            idx[8] = v2.x; idx[9]  = v2.y; idx[10] = v2.z; idx[11] = v2.w;
        } else {
            for (int k = 0; k < EPT * 3; ++k)
                idx[k] = (k < cnt) ? a[(size_t)e0 * 3 + k] : 0;
        }
    } else {
        const long long* a = (const long long*)adj_raw;
        for (int k = 0; k < EPT * 3; ++k)
            idx[k] = (k < cnt) ? (int)a[(size_t)e0 * 3 + k] : 0;
    }
#pragma unroll
    for (int k = 0; k < EPT * 3; ++k)
        idx[k] = min(max(idx[k], 0), n_points - 1);

    const float2* pts2 = (const float2*)points;
    float x[EPT][6];
#pragma unroll
    for (int k = 0; k < EPT * 3; ++k) {
        float2 p = pts2[idx[k]];
        x[k / 3][(k % 3) * 2 + 0] = p.x;
        x[k / 3][(k % 3) * 2 + 1] = p.y;
    }

    float ha[EPT][8], hb[EPT][8];

    // Layer 1: 6 -> 8  (weights loaded once per j, reused across EPT elems)
#pragma unroll
    for (int j = 0; j < 8; ++j) {
        float w0 = sW1[0 * 8 + j], w1 = sW1[1 * 8 + j], w2 = sW1[2 * 8 + j];
        float w3 = sW1[3 * 8 + j], w4 = sW1[4 * 8 + j], w5 = sW1[5 * 8 + j];
        float b = sb1[j];
#pragma unroll
        for (int e = 0; e < EPT; ++e) {
            float acc = b;
            acc = fmaf(x[e][0], w0, acc);
            acc = fmaf(x[e][1], w1, acc);
            acc = fmaf(x[e][2], w2, acc);
            acc = fmaf(x[e][3], w3, acc);
            acc = fmaf(x[e][4], w4, acc);
            acc = fmaf(x[e][5], w5, acc);
            ha[e][j] = fast_sigmoid(acc);
        }
    }

    // Layer 2: 8 -> 8
#pragma unroll
    for (int j = 0; j < 8; ++j) {
        float w0 = sW2[0 * 8 + j], w1 = sW2[1 * 8 + j], w2 = sW2[2 * 8 + j];
        float w3 = sW2[3 * 8 + j], w4 = sW2[4 * 8 + j], w5 = sW2[5 * 8 + j];
        float w6 = sW2[6 * 8 + j], w7 = sW2[7 * 8 + j];
        float b = sb2[j];
#pragma unroll
        for (int e = 0; e < EPT; ++e) {
            float acc = b;
            acc = fmaf(ha[e][0], w0, acc);
            acc = fmaf(ha[e][1], w1, acc);
            acc = fmaf(ha[e][2], w2, acc);
            acc = fmaf(ha[e][3], w3, acc);
            acc = fmaf(ha[e][4], w4, acc);
            acc = fmaf(ha[e][5], w5, acc);
            acc = fmaf(ha[e][6], w6, acc);
            acc = fmaf(ha[e][7], w7, acc);
            hb[e][j] = fast_sigmoid(acc);
        }
    }

    // Layer 3: 8 -> 8
#pragma unroll
    for (int j = 0; j < 8; ++j) {
        float w0 = sW3[0 * 8 + j], w1 = sW3[1 * 8 + j], w2 = sW3[2 * 8 + j];
        float w3 = sW3[3 * 8 + j], w4 = sW3[4 * 8 + j], w5 = sW3[5 * 8 + j];
        float w6 = sW3[6 * 8 + j], w7 = sW3[7 * 8 + j];
        float b = sb3[j];
#pragma unroll
        for (int e = 0; e < EPT; ++e) {
            float acc = b;
            acc = fmaf(hb[e][0], w0, acc);
            acc = fmaf(hb[e][1], w1, acc);
            acc = fmaf(hb[e][2], w2, acc);
            acc = fmaf(hb[e][3], w3, acc);
            acc = fmaf(hb[e][4], w4, acc);
            acc = fmaf(hb[e][5], w5, acc);
            acc = fmaf(hb[e][6], w6, acc);
            acc = fmaf(hb[e][7], w7, acc);
            ha[e][j] = fast_sigmoid(acc);
        }
    }

    // Layer 4: 8 -> 3
    float o[EPT][3];
#pragma unroll
    for (int j = 0; j < 3; ++j) {
        float w0 = sW4[0 * 3 + j], w1 = sW4[1 * 3 + j], w2 = sW4[2 * 3 + j];
        float w3 = sW4[3 * 3 + j], w4 = sW4[4 * 3 + j], w5 = sW4[5 * 3 + j];
        float w6 = sW4[6 * 3 + j], w7 = sW4[7 * 3 + j];
        float b = sb4[j];
#pragma unroll
        for (int e = 0; e < EPT; ++e) {
            float acc = b;
            acc = fmaf(ha[e][0], w0, acc);
            acc = fmaf(ha[e][1], w1, acc);
            acc = fmaf(ha[e][2], w2, acc);
            acc = fmaf(ha[e][3], w3, acc);
            acc = fmaf(ha[e][4], w4, acc);
            acc = fmaf(ha[e][5], w5, acc);
            acc = fmaf(ha[e][6], w6, acc);
            acc = fmaf(ha[e][7], w7, acc);
            o[e][j] = fast_sigmoid(acc);
        }
    }

#pragma unroll
    for (int k = 0; k < EPT * 3; ++k) {
        if (k < cnt) atomicAdd(&out[idx[k]], o[k / 3][k % 3]);
    }
}

extern "C" void kernel_launch(void* const* d_in, const int* in_sizes, int n_in,
                              void* d_out, int out_size) {
    // Resolve inputs by SIZE (robust to metadata ordering).
    const float* points = nullptr;
    const void*  adj    = nullptr;
    const float *W1 = nullptr, *b1 = nullptr, *W2 = nullptr, *b2 = nullptr;
    const float *W3 = nullptr, *b3 = nullptr, *W4 = nullptr, *b4 = nullptr;
    int n_points = 0, n_elems = 0;

    int n8_seen = 0;   // b1, b2, b3 in encounter order
    int n64_seen = 0;  // W2, W3 in encounter order

    for (int i = 0; i < n_in; ++i) {
        int sz = in_sizes[i];
        const void* p = d_in[i];
        if (sz >= 6000000) {            // adjacency (12M entries)
            adj = p; n_elems = sz / 3;
        } else if (sz >= 1000000) {     // points (4M floats)
            points = (const float*)p; n_points = sz / 2;
        } else if (sz == 48) {
            W1 = (const float*)p;
        } else if (sz == 64) {
            if (n64_seen++ == 0) W2 = (const float*)p; else W3 = (const float*)p;
        } else if (sz == 24) {
            W4 = (const float*)p;
        } else if (sz == 8) {
            if (n8_seen == 0) b1 = (const float*)p;
            else if (n8_seen == 1) b2 = (const float*)p;
            else b3 = (const float*)p;
            n8_seen++;
        } else if (sz == 3) {
            b4 = (const float*)p;
        }
    }

    float* out = (float*)d_out;

    zero_detect_kernel<<<(out_size + 255) / 256, 256>>>(
        out, out_size, (const unsigned int*)adj);

    int n_threads = (n_elems + EPT - 1) / EPT;
    mesh_mlp_kernel<<<(n_threads + 255) / 256, 256>>>(
        points, adj, W1, b1, W2, b2, W3, b3, W4, b4, out, n_elems, n_points);
}

// round 10
// speedup vs baseline: 1.7024x; 1.7024x over previous
#include <cuda_runtime.h>

#define EPT 2   // elements per thread

// Packed MLP parameters in constant memory.
// Layout: W1[48] b1[8] W2[64] b2[8] W3[64] b3[8] W4[24] b4[3]
#define OW1 0
#define OB1 48
#define OW2 56
#define OB2 120
#define OW3 128
#define OB3 192
#define OW4 200
#define OB4 224
__constant__ float cP[227];

__device__ int g_adj_is_i64;   // 1 if adjacency buffer is int64-LE, else int32

__global__ void zero_detect_kernel(float* __restrict__ out, int n,
                                   const unsigned int* __restrict__ adj_words) {
    int i = blockIdx.x * blockDim.x + threadIdx.x;
    if (i < n) out[i] = 0.0f;
    if (blockIdx.x == 0 && threadIdx.x == 0) {
        // int64-LE indices < 2^31 => odd words of first 32 entries all zero.
        // Probe stays within first 256 bytes (in-bounds for both layouts).
        int all_zero = 1;
        for (int k = 1; k < 64; k += 2)
            if (adj_words[k] != 0u) { all_zero = 0; break; }
        g_adj_is_i64 = all_zero;
    }
}

__device__ __forceinline__ float fast_sigmoid(float x) {
    // sigmoid(x) = 0.5 * tanh(0.5x) + 0.5 ; tanh.approx.f32 = 1 MUFU op
    float t;
    asm("tanh.approx.f32 %0, %1;" : "=f"(t) : "f"(x * 0.5f));
    return fmaf(t, 0.5f, 0.5f);
}

__global__ __launch_bounds__(256, 4) void mesh_mlp_kernel(
    const float* __restrict__ points,        // [N_POINTS, 2]
    const void*  __restrict__ adj_raw,       // [N_ELEMS, 3] int32 (or int64)
    float* __restrict__ out,                 // [N_POINTS]
    int n_elems, int n_points)
{
    int e0 = (blockIdx.x * blockDim.x + threadIdx.x) * EPT;
    if (e0 >= n_elems) return;

    bool full = (e0 + EPT <= n_elems);
    int cnt = full ? EPT * 3 : (n_elems - e0) * 3;

    int idx[EPT * 3];
    if (!g_adj_is_i64) {                      // uniform branch
        const int* a = (const int*)adj_raw;
        if (full) {
            // 6 ints = 24B, 8B-aligned (e0 even -> byte offset 24*k)
            const int2* a2 = (const int2*)(a + (size_t)e0 * 3);
            int2 v0 = a2[0], v1 = a2[1], v2 = a2[2];
            idx[0] = v0.x; idx[1] = v0.y; idx[2] = v1.x;
            idx[3] = v1.y; idx[4] = v2.x; idx[5] = v2.y;
        } else {
            for (int k = 0; k < EPT * 3; ++k)
                idx[k] = (k < cnt) ? a[(size_t)e0 * 3 + k] : 0;
        }
    } else {
        const long long* a = (const long long*)adj_raw;
        for (int k = 0; k < EPT * 3; ++k)
            idx[k] = (k < cnt) ? (int)a[(size_t)e0 * 3 + k] : 0;
    }
#pragma unroll
    for (int k = 0; k < EPT * 3; ++k)
        idx[k] = min(max(idx[k], 0), n_points - 1);

    const float2* pts2 = (const float2*)points;
    float x[EPT][6];
#pragma unroll
    for (int k = 0; k < EPT * 3; ++k) {
        float2 p = pts2[idx[k]];
        x[k / 3][(k % 3) * 2 + 0] = p.x;
        x[k / 3][(k % 3) * 2 + 1] = p.y;
    }

    float ha[EPT][8], hb[EPT][8];

    // Layer 1: 6 -> 8   (weights via constant/uniform regs: zero L1tex)
#pragma unroll
    for (int j = 0; j < 8; ++j) {
#pragma unroll
        for (int e = 0; e < EPT; ++e) {
            float acc = cP[OB1 + j];
#pragma unroll
            for (int i = 0; i < 6; ++i)
                acc = fmaf(x[e][i], cP[OW1 + i * 8 + j], acc);
            ha[e][j] = fast_sigmoid(acc);
        }
    }

    // Layer 2: 8 -> 8
#pragma unroll
    for (int j = 0; j < 8; ++j) {
#pragma unroll
        for (int e = 0; e < EPT; ++e) {
            float acc = cP[OB2 + j];
#pragma unroll
            for (int i = 0; i < 8; ++i)
                acc = fmaf(ha[e][i], cP[OW2 + i * 8 + j], acc);
            hb[e][j] = fast_sigmoid(acc);
        }
    }

    // Layer 3: 8 -> 8
#pragma unroll
    for (int j = 0; j < 8; ++j) {
#pragma unroll
        for (int e = 0; e < EPT; ++e) {
            float acc = cP[OB3 + j];
#pragma unroll
            for (int i = 0; i < 8; ++i)
                acc = fmaf(hb[e][i], cP[OW3 + i * 8 + j], acc);
            ha[e][j] = fast_sigmoid(acc);
        }
    }

    // Layer 4: 8 -> 3
    float o[EPT][3];
#pragma unroll
    for (int j = 0; j < 3; ++j) {
#pragma unroll
        for (int e = 0; e < EPT; ++e) {
            float acc = cP[OB4 + j];
#pragma unroll
            for (int i = 0; i < 8; ++i)
                acc = fmaf(ha[e][i], cP[OW4 + i * 3 + j], acc);
            o[e][j] = fast_sigmoid(acc);
        }
    }

#pragma unroll
    for (int k = 0; k < EPT * 3; ++k) {
        if (k < cnt) atomicAdd(&out[idx[k]], o[k / 3][k % 3]);
    }
}

extern "C" void kernel_launch(void* const* d_in, const int* in_sizes, int n_in,
                              void* d_out, int out_size) {
    // Resolve inputs by SIZE (robust to metadata ordering).
    const float* points = nullptr;
    const void*  adj    = nullptr;
    const float *W1 = nullptr, *b1 = nullptr, *W2 = nullptr, *b2 = nullptr;
    const float *W3 = nullptr, *b3 = nullptr, *W4 = nullptr, *b4 = nullptr;
    int n_points = 0, n_elems = 0;

    int n8_seen = 0;   // b1, b2, b3 in encounter order
    int n64_seen = 0;  // W2, W3 in encounter order

    for (int i = 0; i < n_in; ++i) {
        int sz = in_sizes[i];
        const void* p = d_in[i];
        if (sz >= 6000000) {            // adjacency (12M entries)
            adj = p; n_elems = sz / 3;
        } else if (sz >= 1000000) {     // points (4M floats)
            points = (const float*)p; n_points = sz / 2;
        } else if (sz == 48) {
            W1 = (const float*)p;
        } else if (sz == 64) {
            if (n64_seen++ == 0) W2 = (const float*)p; else W3 = (const float*)p;
        } else if (sz == 24) {
            W4 = (const float*)p;
        } else if (sz == 8) {
            if (n8_seen == 0) b1 = (const float*)p;
            else if (n8_seen == 1) b2 = (const float*)p;
            else b3 = (const float*)p;
            n8_seen++;
        } else if (sz == 3) {
            b4 = (const float*)p;
        }
    }

    float* out = (float*)d_out;

    // Stage parameters into constant memory (D2D async copies: capturable).
    cudaMemcpyToSymbolAsync(cP, W1, 48 * 4, OW1 * 4, cudaMemcpyDeviceToDevice);
    cudaMemcpyToSymbolAsync(cP, b1,  8 * 4, OB1 * 4, cudaMemcpyDeviceToDevice);
    cudaMemcpyToSymbolAsync(cP, W2, 64 * 4, OW2 * 4, cudaMemcpyDeviceToDevice);
    cudaMemcpyToSymbolAsync(cP, b2,  8 * 4, OB2 * 4, cudaMemcpyDeviceToDevice);
    cudaMemcpyToSymbolAsync(cP, W3, 64 * 4, OW3 * 4, cudaMemcpyDeviceToDevice);
    cudaMemcpyToSymbolAsync(cP, b3,  8 * 4, OB3 * 4, cudaMemcpyDeviceToDevice);
    cudaMemcpyToSymbolAsync(cP, W4, 24 * 4, OW4 * 4, cudaMemcpyDeviceToDevice);
    cudaMemcpyToSymbolAsync(cP, b4,  3 * 4, OB4 * 4, cudaMemcpyDeviceToDevice);

    zero_detect_kernel<<<(out_size + 255) / 256, 256>>>(
        out, out_size, (const unsigned int*)adj);

    int n_threads = (n_elems + EPT - 1) / EPT;
    mesh_mlp_kernel<<<(n_threads + 255) / 256, 256>>>(
        points, adj, out, n_elems, n_points);
}

// round 14
// speedup vs baseline: 1.8350x; 1.0779x over previous
#include <cuda_runtime.h>

#define EPT 2   // elements per thread

// Packed MLP parameters in constant memory.
// Layout: W1[48] b1[8] W2[64] b2[8] W3[64] b3[8] W4[24] b4[3]
#define OW1 0
#define OB1 48
#define OW2 56
#define OB2 120
#define OW3 128
#define OB3 192
#define OW4 200
#define OB4 224
__constant__ float cP[227];

__device__ float g_scratch[227];   // staging for constant bank
__device__ int g_adj_is_i64;       // 1 if adjacency is int64-LE, else int32

// Zero the output; block 0 additionally packs params into g_scratch and
// detects adjacency dtype. One kernel, then ONE memcpyToSymbol D2D.
__global__ void prep_kernel(float* __restrict__ out, int n,
                            const unsigned int* __restrict__ adj_words,
                            const float* __restrict__ W1, const float* __restrict__ b1,
                            const float* __restrict__ W2, const float* __restrict__ b2,
                            const float* __restrict__ W3, const float* __restrict__ b3,
                            const float* __restrict__ W4, const float* __restrict__ b4) {
    int i = blockIdx.x * blockDim.x + threadIdx.x;
    if (i < n) out[i] = 0.0f;
    if (blockIdx.x == 0) {
        int t = threadIdx.x;
        if (t < 48)                 g_scratch[OW1 + t]       = W1[t];
        else if (t < 56)            g_scratch[OB1 + t - 48]  = b1[t - 48];
        else if (t < 120)           g_scratch[OW2 + t - 56]  = W2[t - 56];
        else if (t < 128)           g_scratch[OB2 + t - 120] = b2[t - 120];
        else if (t < 192)           g_scratch[OW3 + t - 128] = W3[t - 128];
        else if (t < 200)           g_scratch[OB3 + t - 192] = b3[t - 192];
        else if (t < 224)           g_scratch[OW4 + t - 200] = W4[t - 200];
        else if (t < 227)           g_scratch[OB4 + t - 224] = b4[t - 224];
        if (t == 255) {
            // int64-LE indices < 2^31 => odd words of first 32 entries all 0.
            // Probe stays within first 256 bytes (in-bounds either way).
            int all_zero = 1;
            for (int k = 1; k < 64; k += 2)
                if (adj_words[k] != 0u) { all_zero = 0; break; }
            g_adj_is_i64 = all_zero;
        }
    }
}

__device__ __forceinline__ float fast_sigmoid(float x) {
    // sigmoid(x) = 0.5 * tanh(0.5x) + 0.5 ; tanh.approx.f32 = 1 MUFU op
    float t;
    asm("tanh.approx.f32 %0, %1;" : "=f"(t) : "f"(x * 0.5f));
    return fmaf(t, 0.5f, 0.5f);
}

__global__ __launch_bounds__(256, 6) void mesh_mlp_kernel(
    const float* __restrict__ points,        // [N_POINTS, 2]
    const void*  __restrict__ adj_raw,       // [N_ELEMS, 3] int32 (or int64)
    float* __restrict__ out,                 // [N_POINTS]
    int n_elems, int n_points)
{
    int e0 = (blockIdx.x * blockDim.x + threadIdx.x) * EPT;
    if (e0 >= n_elems) return;

    bool full = (e0 + EPT <= n_elems);
    int cnt = full ? EPT * 3 : (n_elems - e0) * 3;

    int idx[EPT * 3];
    if (!g_adj_is_i64) {                      // uniform branch
        const int* a = (const int*)adj_raw;
        if (full) {
            // 6 ints = 24B, 8B-aligned (e0 even -> byte offset 24*k)
            const int2* a2 = (const int2*)(a + (size_t)e0 * 3);
            int2 v0 = a2[0], v1 = a2[1], v2 = a2[2];
            idx[0] = v0.x; idx[1] = v0.y; idx[2] = v1.x;
            idx[3] = v1.y; idx[4] = v2.x; idx[5] = v2.y;
        } else {
            for (int k = 0; k < EPT * 3; ++k)
                idx[k] = (k < cnt) ? a[(size_t)e0 * 3 + k] : 0;
        }
    } else {
        const long long* a = (const long long*)adj_raw;
        for (int k = 0; k < EPT * 3; ++k)
            idx[k] = (k < cnt) ? (int)a[(size_t)e0 * 3 + k] : 0;
    }
#pragma unroll
    for (int k = 0; k < EPT * 3; ++k)
        idx[k] = min(max(idx[k], 0), n_points - 1);

    const float2* pts2 = (const float2*)points;
    float x[EPT][6];
#pragma unroll
    for (int k = 0; k < EPT * 3; ++k) {
        float2 p = pts2[idx[k]];
        x[k / 3][(k % 3) * 2 + 0] = p.x;
        x[k / 3][(k % 3) * 2 + 1] = p.y;
    }

    float ha[EPT][8], hb[EPT][8];

    // Layer 1: 6 -> 8   (weights via constant bank: zero L1tex traffic)
#pragma unroll
    for (int j = 0; j < 8; ++j) {
#pragma unroll
        for (int e = 0; e < EPT; ++e) {
            float acc = cP[OB1 + j];
#pragma unroll
            for (int i = 0; i < 6; ++i)
                acc = fmaf(x[e][i], cP[OW1 + i * 8 + j], acc);
            ha[e][j] = fast_sigmoid(acc);
        }
    }

    // Layer 2: 8 -> 8
#pragma unroll
    for (int j = 0; j < 8; ++j) {
#pragma unroll
        for (int e = 0; e < EPT; ++e) {
            float acc = cP[OB2 + j];
#pragma unroll
            for (int i = 0; i < 8; ++i)
                acc = fmaf(ha[e][i], cP[OW2 + i * 8 + j], acc);
            hb[e][j] = fast_sigmoid(acc);
        }
    }

    // Layer 3: 8 -> 8
#pragma unroll
    for (int j = 0; j < 8; ++j) {
#pragma unroll
        for (int e = 0; e < EPT; ++e) {
            float acc = cP[OB3 + j];
#pragma unroll
            for (int i = 0; i < 8; ++i)
                acc = fmaf(hb[e][i], cP[OW3 + i * 8 + j], acc);
            ha[e][j] = fast_sigmoid(acc);
        }
    }

    // Layer 4: 8 -> 3
    float o[EPT][3];
#pragma unroll
    for (int j = 0; j < 3; ++j) {
#pragma unroll
        for (int e = 0; e < EPT; ++e) {
            float acc = cP[OB4 + j];
#pragma unroll
            for (int i = 0; i < 8; ++i)
                acc = fmaf(ha[e][i], cP[OW4 + i * 3 + j], acc);
            o[e][j] = fast_sigmoid(acc);
        }
    }

#pragma unroll
    for (int k = 0; k < EPT * 3; ++k) {
        if (k < cnt) atomicAdd(&out[idx[k]], o[k / 3][k % 3]);
    }
}

extern "C" void kernel_launch(void* const* d_in, const int* in_sizes, int n_in,
                              void* d_out, int out_size) {
    // Resolve inputs by SIZE (robust to metadata ordering).
    const float* points = nullptr;
    const void*  adj    = nullptr;
    const float *W1 = nullptr, *b1 = nullptr, *W2 = nullptr, *b2 = nullptr;
    const float *W3 = nullptr, *b3 = nullptr, *W4 = nullptr, *b4 = nullptr;
    int n_points = 0, n_elems = 0;

    int n8_seen = 0;   // b1, b2, b3 in encounter order
    int n64_seen = 0;  // W2, W3 in encounter order

    for (int i = 0; i < n_in; ++i) {
        int sz = in_sizes[i];
        const void* p = d_in[i];
        if (sz >= 6000000) {            // adjacency (12M entries)
            adj = p; n_elems = sz / 3;
        } else if (sz >= 1000000) {     // points (4M floats)
            points = (const float*)p; n_points = sz / 2;
        } else if (sz == 48) {
            W1 = (const float*)p;
        } else if (sz == 64) {
            if (n64_seen++ == 0) W2 = (const float*)p; else W3 = (const float*)p;
        } else if (sz == 24) {
            W4 = (const float*)p;
        } else if (sz == 8) {
            if (n8_seen == 0) b1 = (const float*)p;
            else if (n8_seen == 1) b2 = (const float*)p;
            else b3 = (const float*)p;
            n8_seen++;
        } else if (sz == 3) {
            b4 = (const float*)p;
        }
    }

    float* out = (float*)d_out;

    prep_kernel<<<(out_size + 255) / 256, 256>>>(
        out, out_size, (const unsigned int*)adj,
        W1, b1, W2, b2, W3, b3, W4, b4);

    // Single D2D copy: scratch -> constant bank (graph memcpy node).
    void* scratch_ptr = nullptr;
    cudaGetSymbolAddress(&scratch_ptr, g_scratch);
    cudaMemcpyToSymbolAsync(cP, scratch_ptr, 227 * sizeof(float), 0,
                            cudaMemcpyDeviceToDevice);

    int n_threads = (n_elems + EPT - 1) / EPT;
    mesh_mlp_kernel<<<(n_threads + 255) / 256, 256>>>(
        points, adj, out, n_elems, n_points);
}

// round 16
// speedup vs baseline: 1.8827x; 1.0260x over previous
#include <cuda_runtime.h>

#define EPT 2   // elements per thread

// Packed MLP parameters in constant memory.
// Layout: W1[48] b1[8] W2[64] b2[8] W3[64] b3[8] W4[24] b4[3]
#define OW1 0
#define OB1 48
#define OW2 56
#define OB2 120
#define OW3 128
#define OB3 192
#define OW4 200
#define OB4 224
__constant__ float cP[227];

__device__ float g_scratch[227];   // staging for constant bank
__device__ int g_adj_is_i64;       // 1 if adjacency is int64-LE, else int32

// Zero the output (float4-vectorized); block 0 additionally packs params into
// g_scratch and detects adjacency dtype. One kernel, then ONE memcpy D2D.
__global__ void prep_kernel(float4* __restrict__ out4, int n4,
                            float* __restrict__ out, int n,
                            const unsigned int* __restrict__ adj_words,
                            const float* __restrict__ W1, const float* __restrict__ b1,
                            const float* __restrict__ W2, const float* __restrict__ b2,
                            const float* __restrict__ W3, const float* __restrict__ b3,
                            const float* __restrict__ W4, const float* __restrict__ b4) {
    int i = blockIdx.x * blockDim.x + threadIdx.x;
    if (i < n4) out4[i] = make_float4(0.f, 0.f, 0.f, 0.f);
    if (i == 0) {   // ragged tail (n not multiple of 4)
        for (int k = n4 * 4; k < n; ++k) out[k] = 0.0f;
    }
    if (blockIdx.x == 0) {
        int t = threadIdx.x;
        if (t < 48)                 g_scratch[OW1 + t]       = W1[t];
        else if (t < 56)            g_scratch[OB1 + t - 48]  = b1[t - 48];
        else if (t < 120)           g_scratch[OW2 + t - 56]  = W2[t - 56];
        else if (t < 128)           g_scratch[OB2 + t - 120] = b2[t - 120];
        else if (t < 192)           g_scratch[OW3 + t - 128] = W3[t - 128];
        else if (t < 200)           g_scratch[OB3 + t - 192] = b3[t - 192];
        else if (t < 224)           g_scratch[OW4 + t - 200] = W4[t - 200];
        else if (t < 227)           g_scratch[OB4 + t - 224] = b4[t - 224];
        if (t == 255) {
            // int64-LE indices < 2^31 => odd words of first 32 entries all 0.
            // Probe stays within first 256 bytes (in-bounds either way).
            int all_zero = 1;
            for (int k = 1; k < 64; k += 2)
                if (adj_words[k] != 0u) { all_zero = 0; break; }
            g_adj_is_i64 = all_zero;
        }
    }
}

__device__ __forceinline__ float fast_sigmoid(float x) {
    // sigmoid(x) = 0.5 * tanh(0.5x) + 0.5 ; tanh.approx.f32 = 1 MUFU op
    float t;
    asm("tanh.approx.f32 %0, %1;" : "=f"(t) : "f"(x * 0.5f));
    return fmaf(t, 0.5f, 0.5f);
}

__global__ __launch_bounds__(128, 12) void mesh_mlp_kernel(
    const float* __restrict__ points,        // [N_POINTS, 2]
    const void*  __restrict__ adj_raw,       // [N_ELEMS, 3] int32 (or int64)
    float* __restrict__ out,                 // [N_POINTS]
    int n_elems, int n_points)
{
    int e0 = (blockIdx.x * blockDim.x + threadIdx.x) * EPT;
    if (e0 >= n_elems) return;

    bool full = (e0 + EPT <= n_elems);
    int cnt = full ? EPT * 3 : (n_elems - e0) * 3;

    int idx[EPT * 3];
    if (!g_adj_is_i64) {                      // uniform branch
        const int* a = (const int*)adj_raw;
        if (full) {
            // 6 ints = 24B, 8B-aligned (e0 even -> byte offset 24*k)
            const int2* a2 = (const int2*)(a + (size_t)e0 * 3);
            int2 v0 = a2[0], v1 = a2[1], v2 = a2[2];
            idx[0] = v0.x; idx[1] = v0.y; idx[2] = v1.x;
            idx[3] = v1.y; idx[4] = v2.x; idx[5] = v2.y;
        } else {
            for (int k = 0; k < EPT * 3; ++k)
                idx[k] = (k < cnt) ? a[(size_t)e0 * 3 + k] : 0;
        }
    } else {
        const long long* a = (const long long*)adj_raw;
        for (int k = 0; k < EPT * 3; ++k)
            idx[k] = (k < cnt) ? (int)a[(size_t)e0 * 3 + k] : 0;
    }
#pragma unroll
    for (int k = 0; k < EPT * 3; ++k)
        idx[k] = min(max(idx[k], 0), n_points - 1);

    const float2* pts2 = (const float2*)points;
    float x[EPT][6];
#pragma unroll
    for (int k = 0; k < EPT * 3; ++k) {
        float2 p = pts2[idx[k]];
        x[k / 3][(k % 3) * 2 + 0] = p.x;
        x[k / 3][(k % 3) * 2 + 1] = p.y;
    }

    float ha[EPT][8], hb[EPT][8];

    // Layer 1: 6 -> 8   (weights via constant bank: zero L1tex traffic)
#pragma unroll
    for (int j = 0; j < 8; ++j) {
#pragma unroll
        for (int e = 0; e < EPT; ++e) {
            float acc = cP[OB1 + j];
#pragma unroll
            for (int i = 0; i < 6; ++i)
                acc = fmaf(x[e][i], cP[OW1 + i * 8 + j], acc);
            ha[e][j] = fast_sigmoid(acc);
        }
    }

    // Layer 2: 8 -> 8
#pragma unroll
    for (int j = 0; j < 8; ++j) {
#pragma unroll
        for (int e = 0; e < EPT; ++e) {
            float acc = cP[OB2 + j];
#pragma unroll
            for (int i = 0; i < 8; ++i)
                acc = fmaf(ha[e][i], cP[OW2 + i * 8 + j], acc);
            hb[e][j] = fast_sigmoid(acc);
        }
    }

    // Layer 3: 8 -> 8
#pragma unroll
    for (int j = 0; j < 8; ++j) {
#pragma unroll
        for (int e = 0; e < EPT; ++e) {
            float acc = cP[OB3 + j];
#pragma unroll
            for (int i = 0; i < 8; ++i)
                acc = fmaf(hb[e][i], cP[OW3 + i * 8 + j], acc);
            ha[e][j] = fast_sigmoid(acc);
        }
    }

    // Layer 4: 8 -> 3
    float o[EPT][3];
#pragma unroll
    for (int j = 0; j < 3; ++j) {
#pragma unroll
        for (int e = 0; e < EPT; ++e) {
            float acc = cP[OB4 + j];
#pragma unroll
            for (int i = 0; i < 8; ++i)
                acc = fmaf(ha[e][i], cP[OW4 + i * 3 + j], acc);
            o[e][j] = fast_sigmoid(acc);
        }
    }

#pragma unroll
    for (int k = 0; k < EPT * 3; ++k) {
        if (k < cnt) atomicAdd(&out[idx[k]], o[k / 3][k % 3]);
    }
}

extern "C" void kernel_launch(void* const* d_in, const int* in_sizes, int n_in,
                              void* d_out, int out_size) {
    // Resolve inputs by SIZE (robust to metadata ordering).
    const float* points = nullptr;
    const void*  adj    = nullptr;
    const float *W1 = nullptr, *b1 = nullptr, *W2 = nullptr, *b2 = nullptr;
    const float *W3 = nullptr, *b3 = nullptr, *W4 = nullptr, *b4 = nullptr;
    int n_points = 0, n_elems = 0;

    int n8_seen = 0;   // b1, b2, b3 in encounter order
    int n64_seen = 0;  // W2, W3 in encounter order

    for (int i = 0; i < n_in; ++i) {
        int sz = in_sizes[i];
        const void* p = d_in[i];
        if (sz >= 6000000) {            // adjacency (12M entries)
            adj = p; n_elems = sz / 3;
        } else if (sz >= 1000000) {     // points (4M floats)
            points = (const float*)p; n_points = sz / 2;
        } else if (sz == 48) {
            W1 = (const float*)p;
        } else if (sz == 64) {
            if (n64_seen++ == 0) W2 = (const float*)p; else W3 = (const float*)p;
        } else if (sz == 24) {
            W4 = (const float*)p;
        } else if (sz == 8) {
            if (n8_seen == 0) b1 = (const float*)p;
            else if (n8_seen == 1) b2 = (const float*)p;
            else b3 = (const float*)p;
            n8_seen++;
        } else if (sz == 3) {
            b4 = (const float*)p;
        }
    }

    float* out = (float*)d_out;

    int n4 = out_size / 4;
    prep_kernel<<<(n4 + 255) / 256, 256>>>(
        (float4*)out, n4, out, out_size, (const unsigned int*)adj,
        W1, b1, W2, b2, W3, b3, W4, b4);

    // Single D2D copy: scratch -> constant bank (graph memcpy node).
    void* scratch_ptr = nullptr;
    cudaGetSymbolAddress(&scratch_ptr, g_scratch);
    cudaMemcpyToSymbolAsync(cP, scratch_ptr, 227 * sizeof(float), 0,
                            cudaMemcpyDeviceToDevice);

    int n_threads = (n_elems + EPT - 1) / EPT;
    mesh_mlp_kernel<<<(n_threads + 127) / 128, 128>>>(
        points, adj, out, n_elems, n_points);
}